// round 6
// baseline (speedup 1.0000x reference)
#include <cuda_runtime.h>
#include <cuda_bf16.h>
#include <cstdint>
#include <cstddef>

// Problem dims
#define M_DIM 4096   // batch
#define N_DIM 2048   // out features
#define K_DIM 2048   // in features

// ---------------------------------------------------------------------------
// Scratch: bf16 hi/lo split of x and weight (static device arrays — allowed)
// ---------------------------------------------------------------------------
__device__ __align__(16) __nv_bfloat16 g_xhi[(size_t)M_DIM * K_DIM];
__device__ __align__(16) __nv_bfloat16 g_xlo[(size_t)M_DIM * K_DIM];
__device__ __align__(16) __nv_bfloat16 g_whi[(size_t)N_DIM * K_DIM];
__device__ __align__(16) __nv_bfloat16 g_wlo[(size_t)N_DIM * K_DIM];

// ---------------------------------------------------------------------------
// Helpers (baseline sm_103 ISA only: cp.async, ldmatrix, mma.sync)
// ---------------------------------------------------------------------------
__device__ __forceinline__ uint32_t smem_u32(const void* p) {
    uint32_t a;
    asm("{ .reg .u64 t; cvta.to.shared.u64 t, %1; cvt.u32.u64 %0, t; }"
        : "=r"(a) : "l"(p));
    return a;
}

__device__ __forceinline__ void cp_async16(uint32_t saddr, const void* gaddr) {
    asm volatile("cp.async.cg.shared.global [%0], [%1], 16;"
                 :: "r"(saddr), "l"(gaddr) : "memory");
}

__device__ __forceinline__ void ldsm4(uint32_t* r, uint32_t addr) {
    asm volatile("ldmatrix.sync.aligned.m8n8.x4.shared.b16 {%0,%1,%2,%3}, [%4];"
                 : "=r"(r[0]), "=r"(r[1]), "=r"(r[2]), "=r"(r[3])
                 : "r"(addr));
}

__device__ __forceinline__ void mma_bf16(float* d, const uint32_t* a,
                                         const uint32_t b0, const uint32_t b1) {
    asm volatile(
        "mma.sync.aligned.m16n8k16.row.col.f32.bf16.bf16.f32 "
        "{%0,%1,%2,%3}, {%4,%5,%6,%7}, {%8,%9}, {%0,%1,%2,%3};"
        : "+f"(d[0]), "+f"(d[1]), "+f"(d[2]), "+f"(d[3])
        : "r"(a[0]), "r"(a[1]), "r"(a[2]), "r"(a[3]), "r"(b0), "r"(b1));
}

// ---------------------------------------------------------------------------
// Split kernels: fp32 -> bf16 hi + bf16 lo  (x = hi + lo to ~16 mantissa bits)
// ---------------------------------------------------------------------------
union BF4 { __nv_bfloat16 b[4]; uint2 u; };

__device__ __forceinline__ void split4(float4 v, __nv_bfloat16* hi,
                                       __nv_bfloat16* lo, size_t elem0) {
    BF4 H, L;
    float f[4] = {v.x, v.y, v.z, v.w};
#pragma unroll
    for (int i = 0; i < 4; i++) {
        H.b[i] = __float2bfloat16(f[i]);
        L.b[i] = __float2bfloat16(f[i] - __bfloat162float(H.b[i]));
    }
    *reinterpret_cast<uint2*>(hi + elem0) = H.u;
    *reinterpret_cast<uint2*>(lo + elem0) = L.u;
}

__global__ void __launch_bounds__(256) split_x_kernel(const float* __restrict__ x) {
    size_t i = (size_t)blockIdx.x * blockDim.x + threadIdx.x;
    const size_t n4 = (size_t)M_DIM * K_DIM / 4;
    if (i < n4) split4(reinterpret_cast<const float4*>(x)[i], g_xhi, g_xlo, 4 * i);
}

__global__ void __launch_bounds__(256) split_w_kernel(const float* __restrict__ w) {
    size_t i = (size_t)blockIdx.x * blockDim.x + threadIdx.x;
    const size_t n4 = (size_t)N_DIM * K_DIM / 4;
    if (i < n4) split4(reinterpret_cast<const float4*>(w)[i], g_whi, g_wlo, 4 * i);
}

// ---------------------------------------------------------------------------
// GEMM: 128x128 CTA tile of out = x @ w^T + bias via 3 bf16 HMMA products
// (hi*hi + hi*lo + lo*hi) with fp32 accumulators in registers.
// 8 warps as 4(m) x 2(n): warp tile 32x64. BK=32, 4-stage cp.async pipeline.
// ---------------------------------------------------------------------------
static constexpr int BK       = 32;                // bf16 elements per K-chunk
static constexpr int KT       = K_DIM / BK;        // 64 iterations
static constexpr int ROW_B    = BK * 2 + 16;       // 80B padded row (conflict-free ldsm)
static constexpr int TILE_B   = 128 * ROW_B;       // 10240 B per 128x32 tile
static constexpr int STAGE_B  = 4 * TILE_B;        // Ahi, Alo, Bhi, Blo = 40960 B
static constexpr int NSTAGE   = 4;
static constexpr int SMEM_DYN = NSTAGE * STAGE_B + 1024;   // ~164.5 KB

__global__ void __launch_bounds__(256, 1)
gemm_kernel(const float* __restrict__ bias, float* __restrict__ out) {
    extern __shared__ char smem_raw[];
    const uint32_t dynbase = (smem_u32(smem_raw) + 1023u) & ~1023u;

    const int tid = threadIdx.x;
    const int wid = tid >> 5;
    const int lid = tid & 31;
    const int bn  = blockIdx.x;        // 0..15
    const int bm  = blockIdx.y;        // 0..31

    const int wm = wid & 3;            // 4 warp rows
    const int wn = wid >> 2;           // 2 warp cols
    const int m0 = wm * 32;            // warp m-offset in CTA tile
    const int n0 = wn * 64;            // warp n-offset in CTA tile

    // gmem bases for the 4 tiles this CTA streams
    const __nv_bfloat16* gbase[4] = {
        g_xhi + (size_t)bm * 128 * K_DIM,
        g_xlo + (size_t)bm * 128 * K_DIM,
        g_whi + (size_t)bn * 128 * K_DIM,
        g_wlo + (size_t)bn * 128 * K_DIM,
    };

    // Per-thread cp.async geometry: 2 chunks of 16B per tile per stage.
    // chunk ci2 in [0,512): row = ci2/4 (0..127), c4 = ci2%4 (16B column).
    int rowi[2], coli[2];
    uint32_t soff[2];
#pragma unroll
    for (int h = 0; h < 2; h++) {
        int ci2 = h * 256 + tid;
        rowi[h] = ci2 >> 2;
        coli[h] = (ci2 & 3) * 8;                         // bf16 elements
        soff[h] = (uint32_t)(rowi[h] * ROW_B + (ci2 & 3) * 16);
    }

    auto load_stage = [&](int s, int kt) {
        const int k0 = kt * BK;
        const uint32_t sb = dynbase + s * STAGE_B;
#pragma unroll
        for (int t = 0; t < 4; t++) {
            const __nv_bfloat16* gp = gbase[t];
#pragma unroll
            for (int h = 0; h < 2; h++) {
                cp_async16(sb + t * TILE_B + soff[h],
                           gp + (size_t)rowi[h] * K_DIM + k0 + coli[h]);
            }
        }
        asm volatile("cp.async.commit_group;" ::: "memory");
    };

    // ldmatrix per-lane base offsets (bytes) within a tile
    const uint32_t lds_row = (uint32_t)(lid & 15);
    const uint32_t lds_chk = (uint32_t)(lid >> 4) * 16;
    const uint32_t aoff = (uint32_t)(m0 + lds_row) * ROW_B + lds_chk;
    const uint32_t boff = (uint32_t)(n0 + lds_row) * ROW_B + lds_chk;

    float acc[2][8][4];
#pragma unroll
    for (int mt = 0; mt < 2; mt++)
#pragma unroll
        for (int nt = 0; nt < 8; nt++)
#pragma unroll
            for (int q = 0; q < 4; q++) acc[mt][nt][q] = 0.0f;

    // Prologue: fill 3 stages
    load_stage(0, 0);
    load_stage(1, 1);
    load_stage(2, 2);

#pragma unroll 1
    for (int kt = 0; kt < KT; kt++) {
        // Complete stage kt (leave newest 2 groups pending)
        asm volatile("cp.async.wait_group 2;" ::: "memory");
        __syncthreads();

        // Refill: stage (kt+3) — overwrites slot consumed at iter kt-1,
        // guarded by the __syncthreads above. Always commit a group so the
        // wait_group accounting stays 1:1.
        if (kt + 3 < KT) load_stage((kt + 3) & 3, kt + 3);
        else asm volatile("cp.async.commit_group;" ::: "memory");

        const uint32_t sb  = dynbase + (kt & 3) * STAGE_B;
        const uint32_t sba = sb;                    // A hi
        const uint32_t sbb = sb + 2 * TILE_B;       // B hi

#pragma unroll
        for (int ks = 0; ks < 2; ks++) {
            const uint32_t kb = (uint32_t)(ks * 32);   // 16 bf16 = 32 bytes

            uint32_t Ahi[2][4], Alo[2][4];
#pragma unroll
            for (int mt = 0; mt < 2; mt++) {
                ldsm4(Ahi[mt], sba + aoff + mt * (16 * ROW_B) + kb);
                ldsm4(Alo[mt], sba + TILE_B + aoff + mt * (16 * ROW_B) + kb);
            }

            uint32_t Bhi[8][2], Blo[8][2];
#pragma unroll
            for (int nt2 = 0; nt2 < 4; nt2++) {
                uint32_t r[4];
                ldsm4(r, sbb + boff + nt2 * (16 * ROW_B) + kb);
                Bhi[nt2 * 2][0] = r[0]; Bhi[nt2 * 2][1] = r[2];
                Bhi[nt2 * 2 + 1][0] = r[1]; Bhi[nt2 * 2 + 1][1] = r[3];
                ldsm4(r, sbb + TILE_B + boff + nt2 * (16 * ROW_B) + kb);
                Blo[nt2 * 2][0] = r[0]; Blo[nt2 * 2][1] = r[2];
                Blo[nt2 * 2 + 1][0] = r[1]; Blo[nt2 * 2 + 1][1] = r[3];
            }

#pragma unroll
            for (int mt = 0; mt < 2; mt++)
#pragma unroll
                for (int nt = 0; nt < 8; nt++) {
                    mma_bf16(acc[mt][nt], Ahi[mt], Bhi[nt][0], Bhi[nt][1]);
                    mma_bf16(acc[mt][nt], Ahi[mt], Blo[nt][0], Blo[nt][1]);
                    mma_bf16(acc[mt][nt], Alo[mt], Bhi[nt][0], Bhi[nt][1]);
                }
        }
    }

    // Epilogue: add bias, store float2 per fragment half.
    const int cq = (lid & 3) * 2;       // col pair within n8 tile
    const int cr = lid >> 2;            // row within m16 tile (0..7)
    const float* bp = bias + bn * 128 + n0;

    float2 bv[8];
#pragma unroll
    for (int nt = 0; nt < 8; nt++)
        bv[nt] = *reinterpret_cast<const float2*>(bp + nt * 8 + cq);

#pragma unroll
    for (int mt = 0; mt < 2; mt++) {
        const int row_g = bm * 128 + m0 + mt * 16 + cr;
        float* orow = out + (size_t)row_g * N_DIM + bn * 128 + n0;
#pragma unroll
        for (int nt = 0; nt < 8; nt++) {
            float2 v0, v1;
            v0.x = acc[mt][nt][0] + bv[nt].x;
            v0.y = acc[mt][nt][1] + bv[nt].y;
            v1.x = acc[mt][nt][2] + bv[nt].x;
            v1.y = acc[mt][nt][3] + bv[nt].y;
            *reinterpret_cast<float2*>(orow + nt * 8 + cq) = v0;
            *reinterpret_cast<float2*>(orow + (size_t)8 * N_DIM + nt * 8 + cq) = v1;
        }
    }
}

// ---------------------------------------------------------------------------
// kernel_launch: split x & w to bf16 hi/lo, then HMMA GEMM. Graph-capturable.
// ---------------------------------------------------------------------------
extern "C" void kernel_launch(void* const* d_in, const int* in_sizes, int n_in,
                              void* d_out, int out_size) {
    const float* x    = (const float*)d_in[0];   // [4096, 2048]
    const float* w    = (const float*)d_in[1];   // [2048, 2048]
    const float* bias = (const float*)d_in[2];   // [2048]
    float* out = (float*)d_out;                  // [4096, 2048]

    (void)in_sizes; (void)n_in; (void)out_size;

    {
        const int n4x = M_DIM * K_DIM / 4;
        split_x_kernel<<<(n4x + 255) / 256, 256>>>(x);
        const int n4w = N_DIM * K_DIM / 4;
        split_w_kernel<<<(n4w + 255) / 256, 256>>>(w);
    }

    static bool attr_set = false;
    if (!attr_set) {
        cudaFuncSetAttribute(gemm_kernel,
                             cudaFuncAttributeMaxDynamicSharedMemorySize, SMEM_DYN);
        attr_set = true;
    }
    dim3 grid(N_DIM / 128, M_DIM / 128);   // (16, 32)
    gemm_kernel<<<grid, 256, SMEM_DYN>>>(bias, out);
}